// round 1
// baseline (speedup 1.0000x reference)
#include <cuda_runtime.h>

#define BB 2
#define LL 16
#define CC 16
#define HH 64
#define WW 64
#define HW (HH*WW)

// Scratch (device globals -- no allocation allowed in kernel_launch)
__device__ float2 g_cum[BB*LL*HW];          // cum flow per (b,l,pixel): {x,y}
__device__ float4 g_imgT[BB*LL*HW*4];       // channel-last images: [((b*L+l)*HW + p)*4 + c4]

// ---------------------------------------------------------------------------
// Kernel 1: cumulative sum of flows over L (sequential, matches jnp.cumsum)
// flows layout: [b][l][2][h][w]
// ---------------------------------------------------------------------------
__global__ void cum_kernel(const float* __restrict__ flows) {
    int i = blockIdx.x * blockDim.x + threadIdx.x;   // [0, BB*HW)
    if (i >= BB * HW) return;
    int b = i >> 12;            // /HW
    int p = i & (HW - 1);
    const float* fb = flows + (size_t)b * LL * 2 * HW;
    float cx = 0.0f, cy = 0.0f;
#pragma unroll
    for (int l = 0; l < LL; l++) {
        cx += fb[(l * 2 + 0) * HW + p];
        cy += fb[(l * 2 + 1) * HW + p];
        g_cum[(b * LL + l) * HW + p] = make_float2(cx, cy);
    }
}

// ---------------------------------------------------------------------------
// Kernel 2: transpose images (B,L,C,H,W) -> channel-last float4 chunks
// ---------------------------------------------------------------------------
__global__ void trans_kernel(const float* __restrict__ images) {
    int o = blockIdx.x * blockDim.x + threadIdx.x;   // [0, BB*LL*HW*4)
    if (o >= BB * LL * HW * 4) return;
    int c4  = o & 3;
    int pix = (o >> 2) & (HW - 1);
    int bl  = o >> 14;
    const float* s = images + (size_t)bl * CC * HW + pix;
    float4 v;
    v.x = s[(c4 * 4 + 0) * HW];
    v.y = s[(c4 * 4 + 1) * HW];
    v.z = s[(c4 * 4 + 2) * HW];
    v.w = s[(c4 * 4 + 3) * HW];
    g_imgT[o] = v;
}

// ---------------------------------------------------------------------------
// Kernel 3: main. One block = 64 pixels x 4 channel-quads for a given (b,t).
// Threads loop k = 0..t, bilinear-gather from channel-last images.
// Blocks with large t launch first (t reversed) for load balance.
// ---------------------------------------------------------------------------
__global__ __launch_bounds__(256) void main_kernel(float* __restrict__ out) {
    __shared__ float2 scum[LL * 64];

    int bt  = blockIdx.x >> 6;        // 64 blocks per (b,t)
    int blk = blockIdx.x & 63;
    int b   = bt >> 4;
    int t   = 15 - (bt & 15);         // heavy blocks first
    int p_base = blk * 64;
    int tid = threadIdx.x;

    // Stage cum for these 64 pixels, all 16 timesteps, into smem.
    const float2* cumb = g_cum + (size_t)b * LL * HW;
    for (int j = tid; j < LL * 64; j += 256) {
        int l  = j >> 6;
        int pl = j & 63;
        scum[j] = cumb[l * HW + p_base + pl];
    }
    __syncthreads();

    int c4 = tid & 3;
    int pl = tid >> 2;
    int p  = p_base + pl;
    int h  = p >> 6;
    int w  = p & 63;

    float bx = (w + 0.5f) * (2.0f / WW) - 1.0f;
    float by = (h + 0.5f) * (2.0f / HH) - 1.0f;
    float2 ct = scum[t * 64 + pl];

    float4 acc = make_float4(0.0f, 0.0f, 0.0f, 0.0f);
    const float4* ib = g_imgT + ((size_t)b * LL * HW) * 4 + c4;

    for (int k = 0; k <= t; k++) {
        float2 ck = scum[k * 64 + pl];
        float gx = bx + (ct.x - ck.x);
        float gy = by + (ct.y - ck.y);

        // wrap: mod(g+1, 2) - 1, then safety
        float ux = gx + 1.0f; ux -= floorf(ux * 0.5f) * 2.0f; gx = ux - 1.0f;
        if (gx < -1.0f) gx += 2.0f;
        float uy = gy + 1.0f; uy -= floorf(uy * 0.5f) * 2.0f; gy = uy - 1.0f;
        if (gy < -1.0f) gy += 2.0f;

        float rx = (gx + 1.0f) * 0.5f * (float)WW - 0.5f;
        float ry = (gy + 1.0f) * 0.5f * (float)HH - 0.5f;

        float fx0 = floorf(rx), fy0 = floorf(ry);
        int x0 = (int)fx0, y0 = (int)fy0;          // x0 in [-1,63], y0 in [-1,63]
        float ax = (fx0 + 1.0f) - rx;              // fx1 - rx
        float sx = rx - fx0;                        // rx - fx0
        float ay = (fy0 + 1.0f) - ry;
        float sy = ry - fy0;

        float mx0 = (x0 >= 0)      ? 1.0f : 0.0f;
        float mx1 = (x0 < WW - 1)  ? 1.0f : 0.0f;  // x1 = x0+1 valid
        float my0 = (y0 >= 0)      ? 1.0f : 0.0f;
        float my1 = (y0 < HH - 1)  ? 1.0f : 0.0f;

        float wa = ax * ay * mx0 * my0;   // (x0, y0)
        float wb = ax * sy * mx0 * my1;   // (x0, y1)
        float wc = sx * ay * mx1 * my0;   // (x1, y0)
        float wd = sx * sy * mx1 * my1;   // (x1, y1)

        int x0c = max(x0, 0), x1c = min(x0 + 1, WW - 1);
        int y0c = max(y0, 0), y1c = min(y0 + 1, HH - 1);

        const float4* kb = ib + (size_t)k * HW * 4;
        float4 va = kb[(y0c * WW + x0c) * 4];
        float4 vb = kb[(y1c * WW + x0c) * 4];
        float4 vc = kb[(y0c * WW + x1c) * 4];
        float4 vd = kb[(y1c * WW + x1c) * 4];

        acc.x += wa * va.x + wb * vb.x + wc * vc.x + wd * vd.x;
        acc.y += wa * va.y + wb * vb.y + wc * vc.y + wd * vd.y;
        acc.z += wa * va.z + wb * vb.z + wc * vc.z + wd * vd.z;
        acc.w += wa * va.w + wb * vb.w + wc * vc.w + wd * vd.w;
    }

    // out layout (B,L,C,H,W)
    float* ob = out + ((size_t)(b * LL + t) * CC + c4 * 4) * HW + p;
    ob[0 * HW] = acc.x;
    ob[1 * HW] = acc.y;
    ob[2 * HW] = acc.z;
    ob[3 * HW] = acc.w;
}

// ---------------------------------------------------------------------------
extern "C" void kernel_launch(void* const* d_in, const int* in_sizes, int n_in,
                              void* d_out, int out_size) {
    // metadata order: flows (262144 fp32), images (2097152 fp32)
    const float* flows  = (const float*)d_in[0];
    const float* images = (const float*)d_in[1];
    if (n_in >= 2 && in_sizes[0] > in_sizes[1]) {   // defensive: swap if order differs
        const float* tmp = flows; flows = images; images = tmp;
    }
    float* out = (float*)d_out;

    cum_kernel<<<(BB * HW + 255) / 256, 256>>>(flows);
    trans_kernel<<<(BB * LL * HW * 4 + 255) / 256, 256>>>(images);
    main_kernel<<<BB * LL * 64, 256>>>(out);
}